// round 5
// baseline (speedup 1.0000x reference)
#include <cuda_runtime.h>
#include <cuda_bf16.h>
#include <cstdint>
#include <stdint.h>
#include <math.h>

// Problem constants
#define NN 2048
#define KK 14
#define CC 512
#define OO 512
#define EE 78
#define BN_EPS 1e-5f

#define MTOT (NN * KK)     // 28672
#define KP 1536            // packed K'' = [ah | al | ah]
#define NCH 24             // KP / 64 chunks

// ---------------- device scratch ----------------
__device__ float g_S1[CC];
__device__ float g_Q[CC];
__device__ float g_u[CC];
__device__ float g_cst;
__device__ __nv_bfloat16 g_Ax[(size_t)MTOT * KP];   // packed X    (88 MB)
__device__ __nv_bfloat16 g_Am[(size_t)MTOT * KP];   // packed agg  (88 MB)
__device__ __nv_bfloat16 g_Bw[2ull * OO * KP];      // packed Wo(0), Wm(1)

__device__ __forceinline__ void split2(float v, __nv_bfloat16& h, __nv_bfloat16& l) {
    h = __float2bfloat16(v);
    l = __float2bfloat16(v - __bfloat162float(h));
}

// ---------------- kernel 0: zero accumulators ----------------
__global__ void k_zero() {
    int c = threadIdx.x;
    g_S1[c] = 0.f;
    g_Q[c]  = 0.f;
}

// ---------------- kernel: pack weights -> bf16 [bh|bh|bl] ----------------
__global__ __launch_bounds__(256) void k_packw(const float* __restrict__ Wm,
                                               const float* __restrict__ Wo) {
    size_t i = (size_t)blockIdx.x * 2048 + threadIdx.x;
#pragma unroll
    for (int r = 0; r < 8; r++, i += 256) {
        int mat = (int)(i >> 18);
        size_t rem = i & 262143;
        size_t o = rem >> 9;
        int c = (int)(rem & 511);
        float v = (mat == 0) ? Wo[rem] : Wm[rem];
        __nv_bfloat16 h, l;
        split2(v, h, l);
        __nv_bfloat16* p = g_Bw + ((size_t)mat * OO + o) * KP;
        p[c] = h; p[512 + c] = h; p[1024 + c] = l;
    }
}

// ---------------- kernel 1: per-channel BN statistics ----------------
__global__ __launch_bounds__(512) void k_stats(const float* __restrict__ x) {
    int c = threadIdx.x;
    int n0 = blockIdx.x * 8;
    float s1a = 0.f, qa = 0.f;
    for (int r = 0; r < 8; r++) {
        const float* p = x + (size_t)(n0 + r) * (KK * CC) + c;
        float g = p[13 * CC];
        float s1 = 0.f, s2 = 0.f, ws = 0.f;
#pragma unroll
        for (int k = 0; k < 13; k++) {
            float d = fabsf(p[k * CC] - g);
            s1 += d;
            s2 += d * d;
            ws += (float)(12 - 2 * k) * d;
        }
        s1a += ws;
        qa  += 13.f * s2 - s1 * s1;
    }
    atomicAdd(&g_S1[c], s1a);
    atomicAdd(&g_Q[c],  qa);
}

// ---------------- kernel 2: finalize stats ----------------
__global__ __launch_bounds__(512) void k_finalize(const float* __restrict__ gamma,
                                                  const float* __restrict__ beta,
                                                  const float* __restrict__ wdir) {
    int c = threadIdx.x;
    const float inv = 1.f / (float)((size_t)NN * EE);
    float mean = 15.f * g_S1[c] * inv;
    float ms   = 225.f * g_Q[c] * inv;
    float var  = ms - mean * mean;
    float gp   = gamma[c] * rsqrtf(var + BN_EPS);
    float w    = wdir[c];
    float u    = gp * w;
    g_u[c] = u;
    float part = beta[c] * w - mean * u;
    __shared__ float sp[16];
    int lane = c & 31, wid = c >> 5;
#pragma unroll
    for (int off = 16; off > 0; off >>= 1)
        part += __shfl_xor_sync(0xffffffffu, part, off);
    if (lane == 0) sp[wid] = part;
    __syncthreads();
    if (c == 0) {
        float s = 0.f;
#pragma unroll
        for (int i = 0; i < 16; i++) s += sp[i];
        g_cst = s;
    }
}

// ---------------- kernel 3: adjacency + aggregation -> packed bf16 A tiles ----------------
__global__ __launch_bounds__(512) void k_adj(const float* __restrict__ x,
                                             const float* __restrict__ adjin,
                                             const int* __restrict__ ei,
                                             const int* __restrict__ ej) {
    int n = blockIdx.x;
    int c = threadIdx.x;
    int lane = c & 31, warp = c >> 5;

    const float* p = x + (size_t)n * (KK * CC) + c;
    float xv[14];
#pragma unroll
    for (int k = 0; k < 14; k++) xv[k] = p[k * CC];
    float g = xv[13];
    float u = g_u[c];

    __shared__ float pp[16][13];
    __shared__ float sp[13];
    __shared__ float W[14][14];
    __shared__ float rn[14];

#pragma unroll
    for (int k = 0; k < 13; k++) {
        float v = fabsf(xv[k] - g) * u;
        v += __shfl_xor_sync(0xffffffffu, v, 16);
        v += __shfl_xor_sync(0xffffffffu, v, 8);
        v += __shfl_xor_sync(0xffffffffu, v, 4);
        v += __shfl_xor_sync(0xffffffffu, v, 2);
        v += __shfl_xor_sync(0xffffffffu, v, 1);
        if (lane == 0) pp[warp][k] = v;
    }
    __syncthreads();
    if (c < 13) {
        float s = 0.f;
#pragma unroll
        for (int w2 = 0; w2 < 16; w2++) s += pp[w2][c];
        sp[c] = s;
    }
    if (c < 196) W[c / 14][c % 14] = adjin[c];
    __syncthreads();
    if (c < EE) {
        int i = ei[c], j = ej[c];
        float z = 15.f * (sp[i] - sp[j]) + g_cst;
        float a = 1.f / (1.f + expf(-4.f * z));
        W[i][j] = 2.f * a * adjin[i * 14 + j];
        W[j][i] = 2.f * (1.f - a) * adjin[j * 14 + i];
    }
    __syncthreads();
    if (c < 14) {
        float s = 0.f;
#pragma unroll
        for (int j = 0; j < 14; j++) s += fabsf(W[c][j]);
        rn[c] = 1.f / fmaxf(s, 1e-12f);
    }
    __syncthreads();

    // pack X rows
    __nv_bfloat16* ax = g_Ax + ((size_t)n * KK) * KP;
#pragma unroll
    for (int k = 0; k < 14; k++) {
        __nv_bfloat16 h, l;
        split2(xv[k], h, l);
        __nv_bfloat16* q = ax + (size_t)k * KP;
        q[c] = h; q[512 + c] = l; q[1024 + c] = h;
    }
    // aggregate + pack
    __nv_bfloat16* am = g_Am + ((size_t)n * KK) * KP;
#pragma unroll
    for (int i = 0; i < 14; i++) {
        float acc = 0.f;
#pragma unroll
        for (int j = 0; j < 14; j++) acc += W[i][j] * xv[j];
        acc *= rn[i];
        __nv_bfloat16 h, l;
        split2(acc, h, l);
        __nv_bfloat16* q = am + (size_t)i * KP;
        q[c] = h; q[512 + c] = l; q[1024 + c] = h;
    }
}

// ---------------- kernel 4: bf16 mma.sync GEMM, ldmatrix + cp.async pipeline ----------------
// C[m,o] = sum_k A[m,k] * B[o,k], A packed [ah|al|ah], B packed [bh|bh|bl].
// Block: M=64 x N=512 (A read once), 8 warps each 64x64, K streamed in 64-col chunks.
#define SA_BYTES 8192           // 64 rows x 128B
#define SB_BYTES 65536          // 512 rows x 128B
#define STAGE_B (SA_BYTES + SB_BYTES)
#define SMEM_TC (2 * STAGE_B)   // 147456

__device__ __forceinline__ void cpa16(uint32_t dst, const void* src) {
    asm volatile("cp.async.cg.shared.global [%0], [%1], 16;" :: "r"(dst), "l"(src));
}

#define LDSM_X4(r, addr)                                                      \
    asm volatile("ldmatrix.sync.aligned.m8n8.x4.shared.b16 {%0,%1,%2,%3}, [%4];" \
                 : "=r"((r)[0]), "=r"((r)[1]), "=r"((r)[2]), "=r"((r)[3])     \
                 : "r"(addr))

#define MMA_BF16(Cr, A0, A1, A2, A3, B0, B1)                                  \
    asm volatile("mma.sync.aligned.m16n8k16.row.col.f32.bf16.bf16.f32 "        \
                 "{%0,%1,%2,%3}, {%4,%5,%6,%7}, {%8,%9}, {%0,%1,%2,%3};\n"     \
                 : "+f"(Cr[0]), "+f"(Cr[1]), "+f"(Cr[2]), "+f"(Cr[3])          \
                 : "r"(A0), "r"(A1), "r"(A2), "r"(A3), "r"(B0), "r"(B1))

__device__ __forceinline__ void load_chunk(uint32_t sb, int stg, int t, int m0, int tid,
                                           const __nv_bfloat16* __restrict__ A,
                                           const __nv_bfloat16* __restrict__ B) {
    uint32_t base = sb + (uint32_t)stg * STAGE_B;
    const __nv_bfloat16* Ag = A + (size_t)m0 * KP + t * 64;
    const __nv_bfloat16* Bg = B + t * 64;
#pragma unroll
    for (int i = 0; i < 2; i++) {                 // A: 512 chunks of 16B
        int idx = tid + i * 256;
        int r = idx >> 3, c = idx & 7;
        uint32_t off = (uint32_t)r * 128 + (uint32_t)c * 16;
        cpa16(base + (off ^ ((off >> 3) & 0x70)), Ag + (size_t)r * KP + c * 8);
    }
#pragma unroll
    for (int i = 0; i < 16; i++) {                // B: 4096 chunks of 16B
        int idx = tid + i * 256;
        int r = idx >> 3, c = idx & 7;
        uint32_t off = (uint32_t)r * 128 + (uint32_t)c * 16;
        cpa16(base + SA_BYTES + (off ^ ((off >> 3) & 0x70)), Bg + (size_t)r * KP + c * 8);
    }
}

template <bool MERGED>
__global__ __launch_bounds__(256, 1) void k_tc(const __nv_bfloat16* __restrict__ A,
                                               const __nv_bfloat16* __restrict__ B,
                                               float* __restrict__ out) {
    extern __shared__ char smem[];
    uint32_t sb = (uint32_t)__cvta_generic_to_shared(smem);
    int tid = threadIdx.x;
    int w = tid >> 5, l = tid & 31;
    int m0 = blockIdx.x * 64;
    int lr = l & 15, lh = l >> 4;   // ldmatrix row / 16B half

    float acc[4][8][4];
#pragma unroll
    for (int mt = 0; mt < 4; mt++)
#pragma unroll
        for (int nt = 0; nt < 8; nt++)
#pragma unroll
            for (int i = 0; i < 4; i++) acc[mt][nt][i] = 0.f;

    load_chunk(sb, 0, 0, m0, tid, A, B);
    asm volatile("cp.async.commit_group;" ::: "memory");
    load_chunk(sb, 1, 1, m0, tid, A, B);
    asm volatile("cp.async.commit_group;" ::: "memory");

    for (int t = 0; t < NCH; t++) {
        int b = t & 1;
        if (t < NCH - 1) asm volatile("cp.async.wait_group 1;" ::: "memory");
        else             asm volatile("cp.async.wait_group 0;" ::: "memory");
        __syncthreads();

        uint32_t aB = sb + (uint32_t)b * STAGE_B;
        uint32_t bB = aB + SA_BYTES;
#pragma unroll
        for (int ks = 0; ks < 4; ks++) {
            uint32_t af[4][4], bf[4][4];
#pragma unroll
            for (int mt = 0; mt < 4; mt++) {
                uint32_t off = (uint32_t)(mt * 16 + lr) * 128 + (uint32_t)lh * 16 + ks * 32;
                LDSM_X4(af[mt], aB + (off ^ ((off >> 3) & 0x70)));
            }
#pragma unroll
            for (int i = 0; i < 4; i++) {
                uint32_t off = (uint32_t)(w * 64 + i * 16 + lr) * 128 + (uint32_t)lh * 16 + ks * 32;
                LDSM_X4(bf[i], bB + (off ^ ((off >> 3) & 0x70)));
            }
#pragma unroll
            for (int mt = 0; mt < 4; mt++)
#pragma unroll
                for (int i = 0; i < 4; i++) {
                    MMA_BF16(acc[mt][2 * i],     af[mt][0], af[mt][1], af[mt][2], af[mt][3], bf[i][0], bf[i][2]);
                    MMA_BF16(acc[mt][2 * i + 1], af[mt][0], af[mt][1], af[mt][2], af[mt][3], bf[i][1], bf[i][3]);
                }
        }
        __syncthreads();

        if (t + 2 < NCH) {
            load_chunk(sb, b, t + 2, m0, tid, A, B);
            asm volatile("cp.async.commit_group;" ::: "memory");
        }
    }

    // epilogue
    int gid = l >> 2, tig = l & 3;
#pragma unroll
    for (int mt = 0; mt < 4; mt++) {
#pragma unroll
        for (int nt = 0; nt < 8; nt++) {
            float* p0 = out + (size_t)(m0 + mt * 16 + gid) * OO + w * 64 + nt * 8 + tig * 2;
            float* p1 = p0 + 8 * OO;
            if (MERGED) {
                float2 v0 = *(float2*)p0;
                float2 v1 = *(float2*)p1;
                v0.x += fmaxf(acc[mt][nt][0], 0.f);
                v0.y += fmaxf(acc[mt][nt][1], 0.f);
                v1.x += fmaxf(acc[mt][nt][2], 0.f);
                v1.y += fmaxf(acc[mt][nt][3], 0.f);
                *(float2*)p0 = v0;
                *(float2*)p1 = v1;
            } else {
                *(float2*)p0 = make_float2(acc[mt][nt][0], acc[mt][nt][1]);
                *(float2*)p1 = make_float2(acc[mt][nt][2], acc[mt][nt][3]);
            }
        }
    }
}

// ---------------- launch ----------------
extern "C" void kernel_launch(void* const* d_in, const int* in_sizes, int n_in,
                              void* d_out, int out_size) {
    const float* x     = (const float*)d_in[0];
    const float* adj   = (const float*)d_in[1];
    const int*   ei    = (const int*)d_in[2];
    const int*   ej    = (const int*)d_in[3];
    const float* gamma = (const float*)d_in[4];
    const float* beta  = (const float*)d_in[5];
    const float* wdir  = (const float*)d_in[6];
    const float* Wm    = (const float*)d_in[7];
    const float* Wo    = (const float*)d_in[8];
    float* out = (float*)d_out;

    cudaFuncSetAttribute(k_tc<false>, cudaFuncAttributeMaxDynamicSharedMemorySize, SMEM_TC);
    cudaFuncSetAttribute(k_tc<true>,  cudaFuncAttributeMaxDynamicSharedMemorySize, SMEM_TC);

    k_zero<<<1, CC>>>();
    k_packw<<<(2 * OO * CC) / 2048, 256>>>(Wm, Wo);
    k_stats<<<NN / 8, CC>>>(x);
    k_finalize<<<1, CC>>>(gamma, beta, wdir);
    k_adj<<<NN, CC>>>(x, adj, ei, ej);

    __nv_bfloat16* Ax; cudaGetSymbolAddress((void**)&Ax, g_Ax);
    __nv_bfloat16* Am; cudaGetSymbolAddress((void**)&Am, g_Am);
    __nv_bfloat16* Bw; cudaGetSymbolAddress((void**)&Bw, g_Bw);

    k_tc<false><<<MTOT / 64, 256, SMEM_TC>>>(Ax, Bw, out);              // out  = X @ Wo^T
    k_tc<true ><<<MTOT / 64, 256, SMEM_TC>>>(Am, Bw + (size_t)OO * KP, out); // out += relu(agg @ Wm^T)
}

// round 6
// speedup vs baseline: 1.6284x; 1.6284x over previous
#include <cuda_runtime.h>
#include <cuda_fp16.h>
#include <cstdint>
#include <stdint.h>
#include <math.h>

#define NN 2048
#define KK 14
#define CC 512
#define OO 512
#define EE 78
#define BN_EPS 1e-5f
#define MTOT (NN * KK)     // 28672

// ---------------- device scratch ----------------
__device__ float g_S1[CC];
__device__ float g_Q[CC];
__device__ float g_u[CC];
__device__ float g_cst;
__device__ __half g_Ah[(size_t)MTOT * CC];     // fp16 X (28 MB)
__device__ __half g_Bh[2ull * OO * CC];        // fp16 Wo(0), Wm(1)
__device__ float  g_Ym[(size_t)MTOT * OO];     // X @ Wm^T (58 MB)
__device__ float  g_Yo[(size_t)MTOT * OO];     // X @ Wo^T (58 MB)
__device__ float  g_An[NN * 196];              // normalized adjacency

// ---------------- kernel 0: zero accumulators ----------------
__global__ void k_zero() {
    int c = threadIdx.x;
    g_S1[c] = 0.f;
    g_Q[c]  = 0.f;
}

// ---------------- pack weights to fp16 ----------------
__global__ __launch_bounds__(256) void k_packw(const float* __restrict__ Wm,
                                               const float* __restrict__ Wo) {
    int i = blockIdx.x * 1024 + threadIdx.x;
#pragma unroll
    for (int r = 0; r < 4; r++, i += 256) {
        g_Bh[i]          = __float2half(Wo[i]);
        g_Bh[262144 + i] = __float2half(Wm[i]);
    }
}

// ---------------- per-channel BN statistics ----------------
__global__ __launch_bounds__(512) void k_stats(const float* __restrict__ x) {
    int c = threadIdx.x;
    int n0 = blockIdx.x * 8;
    float s1a = 0.f, qa = 0.f;
    for (int r = 0; r < 8; r++) {
        const float* p = x + (size_t)(n0 + r) * (KK * CC) + c;
        float g = p[13 * CC];
        float s1 = 0.f, s2 = 0.f, ws = 0.f;
#pragma unroll
        for (int k = 0; k < 13; k++) {
            float d = fabsf(p[k * CC] - g);
            s1 += d;
            s2 += d * d;
            ws += (float)(12 - 2 * k) * d;
        }
        s1a += ws;
        qa  += 13.f * s2 - s1 * s1;
    }
    atomicAdd(&g_S1[c], s1a);
    atomicAdd(&g_Q[c],  qa);
}

// ---------------- finalize stats ----------------
__global__ __launch_bounds__(512) void k_finalize(const float* __restrict__ gamma,
                                                  const float* __restrict__ beta,
                                                  const float* __restrict__ wdir) {
    int c = threadIdx.x;
    const float inv = 1.f / (float)((size_t)NN * EE);
    float mean = 15.f * g_S1[c] * inv;
    float ms   = 225.f * g_Q[c] * inv;
    float var  = ms - mean * mean;
    float gp   = gamma[c] * rsqrtf(var + BN_EPS);
    float w    = wdir[c];
    float u    = gp * w;
    g_u[c] = u;
    float part = beta[c] * w - mean * u;
    __shared__ float sp[16];
    int lane = c & 31, wid = c >> 5;
#pragma unroll
    for (int off = 16; off > 0; off >>= 1)
        part += __shfl_xor_sync(0xffffffffu, part, off);
    if (lane == 0) sp[wid] = part;
    __syncthreads();
    if (c == 0) {
        float s = 0.f;
#pragma unroll
        for (int i = 0; i < 16; i++) s += sp[i];
        g_cst = s;
    }
}

// ---------------- adjacency (normalized) + fp16 pack of X ----------------
__global__ __launch_bounds__(512) void k_adjW(const float* __restrict__ x,
                                              const float* __restrict__ adjin,
                                              const int* __restrict__ ei,
                                              const int* __restrict__ ej) {
    int n = blockIdx.x;
    int c = threadIdx.x;
    int lane = c & 31, warp = c >> 5;

    const float* p = x + (size_t)n * (KK * CC) + c;
    float xv[14];
#pragma unroll
    for (int k = 0; k < 14; k++) xv[k] = p[k * CC];
    float g = xv[13];
    float u = g_u[c];

    __shared__ float pp[16][13];
    __shared__ float sp[13];
    __shared__ float W[14][14];
    __shared__ float rn[14];

#pragma unroll
    for (int k = 0; k < 13; k++) {
        float v = fabsf(xv[k] - g) * u;
        v += __shfl_xor_sync(0xffffffffu, v, 16);
        v += __shfl_xor_sync(0xffffffffu, v, 8);
        v += __shfl_xor_sync(0xffffffffu, v, 4);
        v += __shfl_xor_sync(0xffffffffu, v, 2);
        v += __shfl_xor_sync(0xffffffffu, v, 1);
        if (lane == 0) pp[warp][k] = v;
    }
    // pack X to fp16 while reduction settles
    __half* ah = g_Ah + ((size_t)n * KK) * CC + c;
#pragma unroll
    for (int k = 0; k < 14; k++) ah[k * CC] = __float2half(xv[k]);

    __syncthreads();
    if (c < 13) {
        float s = 0.f;
#pragma unroll
        for (int w2 = 0; w2 < 16; w2++) s += pp[w2][c];
        sp[c] = s;
    }
    if (c < 196) W[c / 14][c % 14] = adjin[c];
    __syncthreads();
    if (c < EE) {
        int i = ei[c], j = ej[c];
        float z = 15.f * (sp[i] - sp[j]) + g_cst;
        float a = 1.f / (1.f + expf(-4.f * z));
        W[i][j] = 2.f * a * adjin[i * 14 + j];
        W[j][i] = 2.f * (1.f - a) * adjin[j * 14 + i];
    }
    __syncthreads();
    if (c < 14) {
        float s = 0.f;
#pragma unroll
        for (int j = 0; j < 14; j++) s += fabsf(W[c][j]);
        rn[c] = 1.f / fmaxf(s, 1e-12f);
    }
    __syncthreads();
    if (c < 196) g_An[n * 196 + c] = W[c / 14][c % 14] * rn[c / 14];
}

// ---------------- dual fp16 mma GEMM: Ym = X@Wm^T, Yo = X@Wo^T ----------------
// Block M=64 x (128 cols of BOTH matrices). 16 warps: 2m x 4n x 2mat, warp 32x32.
#define SA_B 8192                 // 64 x 128B
#define SB_B 32768                // 2 x 128 x 128B
#define STG (SA_B + SB_B)         // 40960
#define SMEM_G (2 * STG)          // 81920

__device__ __forceinline__ void cpa16(uint32_t dst, const void* src) {
    asm volatile("cp.async.cg.shared.global [%0], [%1], 16;" :: "r"(dst), "l"(src));
}
#define LDSM_X4(r, addr)                                                      \
    asm volatile("ldmatrix.sync.aligned.m8n8.x4.shared.b16 {%0,%1,%2,%3}, [%4];" \
                 : "=r"((r)[0]), "=r"((r)[1]), "=r"((r)[2]), "=r"((r)[3])     \
                 : "r"(addr))
#define MMA_F16(Cr, A0, A1, A2, A3, B0, B1)                                   \
    asm volatile("mma.sync.aligned.m16n8k16.row.col.f32.f16.f16.f32 "          \
                 "{%0,%1,%2,%3}, {%4,%5,%6,%7}, {%8,%9}, {%0,%1,%2,%3};\n"     \
                 : "+f"(Cr[0]), "+f"(Cr[1]), "+f"(Cr[2]), "+f"(Cr[3])          \
                 : "r"(A0), "r"(A1), "r"(A2), "r"(A3), "r"(B0), "r"(B1))

__device__ __forceinline__ void g_load_chunk(uint32_t sb, int stg, int t,
                                             int m0, int o0, int tid) {
    uint32_t base = sb + (uint32_t)stg * STG;
    const __half* Ag = g_Ah + (size_t)m0 * CC + t * 64;
    const __half* Bg = g_Bh + t * 64;
    {   // A: 512 x 16B
        int r = tid >> 3, c = tid & 7;
        uint32_t off = (uint32_t)r * 128 + (uint32_t)c * 16;
        cpa16(base + (off ^ ((off >> 3) & 0x70)), Ag + (size_t)r * CC + c * 8);
    }
#pragma unroll
    for (int i = 0; i < 4; i++) {   // B: 2048 x 16B (2 streams x 128 rows)
        int idx = tid + i * 512;
        int s = idx >> 10;                 // matrix 0/1
        int r = (idx >> 3) & 127, c = idx & 7;
        uint32_t off = (uint32_t)r * 128 + (uint32_t)c * 16;
        cpa16(base + SA_B + (uint32_t)s * 16384 + (off ^ ((off >> 3) & 0x70)),
              Bg + ((size_t)s * OO * CC) + (size_t)(o0 + r) * CC + c * 8);
    }
}

__global__ __launch_bounds__(512, 1) void k_gemm() {
    extern __shared__ char smem[];
    uint32_t sb = (uint32_t)__cvta_generic_to_shared(smem);
    int tid = threadIdx.x;
    int w = tid >> 5, l = tid & 31;
    int wm = w & 1;            // m half (32 rows)
    int wn = (w >> 1) & 3;     // n quarter (32 cols)
    int wmat = w >> 3;         // 0 = Yo, 1 = Ym
    int m0 = blockIdx.x * 64;
    int o0 = blockIdx.y * 128;
    int lr = l & 15, lh = l >> 4;

    float acc[2][4][4];
#pragma unroll
    for (int mt = 0; mt < 2; mt++)
#pragma unroll
        for (int nt = 0; nt < 4; nt++)
#pragma unroll
            for (int i = 0; i < 4; i++) acc[mt][nt][i] = 0.f;

    g_load_chunk(sb, 0, 0, m0, o0, tid);
    asm volatile("cp.async.commit_group;" ::: "memory");
    g_load_chunk(sb, 1, 1, m0, o0, tid);
    asm volatile("cp.async.commit_group;" ::: "memory");

    const int NCH2 = CC / 64;   // 8
    for (int t = 0; t < NCH2; t++) {
        int b = t & 1;
        if (t < NCH2 - 1) asm volatile("cp.async.wait_group 1;" ::: "memory");
        else              asm volatile("cp.async.wait_group 0;" ::: "memory");
        __syncthreads();

        uint32_t aB = sb + (uint32_t)b * STG;
        uint32_t bB = aB + SA_B + (uint32_t)wmat * 16384;
#pragma unroll
        for (int ks = 0; ks < 4; ks++) {
            uint32_t af[2][4], bf[2][4];
#pragma unroll
            for (int mt = 0; mt < 2; mt++) {
                uint32_t off = (uint32_t)(wm * 32 + mt * 16 + lr) * 128 + (uint32_t)lh * 16 + ks * 32;
                LDSM_X4(af[mt], aB + (off ^ ((off >> 3) & 0x70)));
            }
#pragma unroll
            for (int i = 0; i < 2; i++) {
                uint32_t off = (uint32_t)(wn * 32 + i * 16 + lr) * 128 + (uint32_t)lh * 16 + ks * 32;
                LDSM_X4(bf[i], bB + (off ^ ((off >> 3) & 0x70)));
            }
#pragma unroll
            for (int mt = 0; mt < 2; mt++)
#pragma unroll
                for (int i = 0; i < 2; i++) {
                    MMA_F16(acc[mt][2 * i],     af[mt][0], af[mt][1], af[mt][2], af[mt][3], bf[i][0], bf[i][2]);
                    MMA_F16(acc[mt][2 * i + 1], af[mt][0], af[mt][1], af[mt][2], af[mt][3], bf[i][1], bf[i][3]);
                }
        }
        __syncthreads();

        if (t + 2 < NCH2) {
            g_load_chunk(sb, b, t + 2, m0, o0, tid);
            asm volatile("cp.async.commit_group;" ::: "memory");
        }
    }

    float* Yp = wmat ? g_Ym : g_Yo;
    int gid = l >> 2, tig = l & 3;
#pragma unroll
    for (int mt = 0; mt < 2; mt++) {
#pragma unroll
        for (int nt = 0; nt < 4; nt++) {
            float* p0 = Yp + (size_t)(m0 + wm * 32 + mt * 16 + gid) * OO + o0 + wn * 32 + nt * 8 + tig * 2;
            *(float2*)p0            = make_float2(acc[mt][nt][0], acc[mt][nt][1]);
            *(float2*)(p0 + 8 * OO) = make_float2(acc[mt][nt][2], acc[mt][nt][3]);
        }
    }
}

// ---------------- post: out = relu(An @ Ym) + Yo ----------------
__global__ __launch_bounds__(512) void k_post(float* __restrict__ out) {
    int n = blockIdx.x;
    int c = threadIdx.x;
    __shared__ float An[196];
    if (c < 196) An[c] = g_An[n * 196 + c];
    __syncthreads();

    size_t base = (size_t)n * KK * OO + c;
    float ym[14];
#pragma unroll
    for (int j = 0; j < 14; j++) ym[j] = g_Ym[base + j * OO];
#pragma unroll
    for (int i = 0; i < 14; i++) {
        float s = 0.f;
#pragma unroll
        for (int j = 0; j < 14; j++) s += An[i * 14 + j] * ym[j];
        out[base + i * OO] = fmaxf(s, 0.f) + g_Yo[base + i * OO];
    }
}

// ---------------- launch ----------------
extern "C" void kernel_launch(void* const* d_in, const int* in_sizes, int n_in,
                              void* d_out, int out_size) {
    const float* x     = (const float*)d_in[0];
    const float* adj   = (const float*)d_in[1];
    const int*   ei    = (const int*)d_in[2];
    const int*   ej    = (const int*)d_in[3];
    const float* gamma = (const float*)d_in[4];
    const float* beta  = (const float*)d_in[5];
    const float* wdir  = (const float*)d_in[6];
    const float* Wm    = (const float*)d_in[7];
    const float* Wo    = (const float*)d_in[8];
    float* out = (float*)d_out;

    cudaFuncSetAttribute(k_gemm, cudaFuncAttributeMaxDynamicSharedMemorySize, SMEM_G);

    k_zero<<<1, CC>>>();
    k_packw<<<(OO * CC) / 1024, 256>>>(Wm, Wo);
    k_stats<<<NN / 8, CC>>>(x);
    k_finalize<<<1, CC>>>(gamma, beta, wdir);
    k_adjW<<<NN, CC>>>(x, adj, ei, ej);

    dim3 grid(MTOT / 64, OO / 128);   // 448 x 4
    k_gemm<<<grid, 512, SMEM_G>>>();
    k_post<<<NN, 512>>>(out);
}

// round 7
// speedup vs baseline: 2.3784x; 1.4605x over previous
#include <cuda_runtime.h>
#include <cuda_fp16.h>
#include <cstdint>
#include <stdint.h>
#include <math.h>

#define NN 2048
#define KK 14
#define CC 512
#define OO 512
#define EE 78
#define BN_EPS 1e-5f
#define MTOT (NN * KK)     // 28672

// ---------------- device scratch ----------------
__device__ float g_S1[CC];
__device__ float g_Q[CC];
__device__ __half g_Ah[(size_t)MTOT * CC];     // fp16 X    (28 MB)
__device__ __half g_Ag[(size_t)MTOT * CC];     // fp16 agg  (28 MB)
__device__ __half g_Bh[2ull * OO * CC];        // fp16 Wo(0), Wm(1)

// ---------------- kernel 0: zero accumulators ----------------
__global__ void k_zero() {
    int c = threadIdx.x;
    g_S1[c] = 0.f;
    g_Q[c]  = 0.f;
}

// ---------------- pack weights to fp16 ----------------
__global__ __launch_bounds__(256) void k_packw(const float* __restrict__ Wm,
                                               const float* __restrict__ Wo) {
    int i = blockIdx.x * 1024 + threadIdx.x;
#pragma unroll
    for (int r = 0; r < 4; r++, i += 256) {
        g_Bh[i]            = __float2half(Wo[i]);
        g_Bh[OO * CC + i]  = __float2half(Wm[i]);
    }
}

// ---------------- per-channel BN statistics ----------------
__global__ __launch_bounds__(512) void k_stats(const float* __restrict__ x) {
    int c = threadIdx.x;
    int n0 = blockIdx.x * 8;
    float s1a = 0.f, qa = 0.f;
    for (int r = 0; r < 8; r++) {
        const float* p = x + (size_t)(n0 + r) * (KK * CC) + c;
        float g = p[13 * CC];
        float s1 = 0.f, s2 = 0.f, ws = 0.f;
#pragma unroll
        for (int k = 0; k < 13; k++) {
            float d = fabsf(p[k * CC] - g);
            s1 += d;
            s2 += d * d;
            ws += (float)(12 - 2 * k) * d;
        }
        s1a += ws;
        qa  += 13.f * s2 - s1 * s1;
    }
    atomicAdd(&g_S1[c], s1a);
    atomicAdd(&g_Q[c],  qa);
}

// ---------------- adjacency + aggregation + fp16 pack (finalize folded in) ----------------
__global__ __launch_bounds__(512) void k_adjW(const float* __restrict__ x,
                                              const float* __restrict__ adjin,
                                              const int* __restrict__ ei,
                                              const int* __restrict__ ej,
                                              const float* __restrict__ gamma,
                                              const float* __restrict__ beta,
                                              const float* __restrict__ wdir) {
    int n = blockIdx.x;
    int c = threadIdx.x;
    int lane = c & 31, warp = c >> 5;

    // --- inline finalize: u[c] and cst from global stats ---
    const float inv = 1.f / (float)((size_t)NN * EE);
    float mean = 15.f * g_S1[c] * inv;
    float ms   = 225.f * g_Q[c] * inv;
    float var  = ms - mean * mean;
    float w    = wdir[c];
    float u    = gamma[c] * rsqrtf(var + BN_EPS) * w;
    float part = beta[c] * w - mean * u;

    __shared__ float red[16];
    __shared__ float s_cst;
#pragma unroll
    for (int off = 16; off > 0; off >>= 1)
        part += __shfl_xor_sync(0xffffffffu, part, off);
    if (lane == 0) red[warp] = part;

    const float* p = x + (size_t)n * (KK * CC) + c;
    float xv[14];
#pragma unroll
    for (int k = 0; k < 14; k++) xv[k] = p[k * CC];
    float g = xv[13];

    __syncthreads();
    if (c == 0) {
        float s = 0.f;
#pragma unroll
        for (int i = 0; i < 16; i++) s += red[i];
        s_cst = s;
    }

    __shared__ float pp[16][13];
    __shared__ float sp[13];
    __shared__ float W[14][14];
    __shared__ float rn[14];

#pragma unroll
    for (int k = 0; k < 13; k++) {
        float v = fabsf(xv[k] - g) * u;
        v += __shfl_xor_sync(0xffffffffu, v, 16);
        v += __shfl_xor_sync(0xffffffffu, v, 8);
        v += __shfl_xor_sync(0xffffffffu, v, 4);
        v += __shfl_xor_sync(0xffffffffu, v, 2);
        v += __shfl_xor_sync(0xffffffffu, v, 1);
        if (lane == 0) pp[warp][k] = v;
    }

    // pack X to fp16 while reduction settles
    __half* ah = g_Ah + ((size_t)n * KK) * CC + c;
#pragma unroll
    for (int k = 0; k < 14; k++) ah[k * CC] = __float2half(xv[k]);

    __syncthreads();
    if (c < 13) {
        float s = 0.f;
#pragma unroll
        for (int w2 = 0; w2 < 16; w2++) s += pp[w2][c];
        sp[c] = s;
    }
    if (c < 196) W[c / 14][c % 14] = adjin[c];
    __syncthreads();
    if (c < EE) {
        int i = ei[c], j = ej[c];
        float z = 15.f * (sp[i] - sp[j]) + s_cst;
        float a = 1.f / (1.f + expf(-4.f * z));
        W[i][j] = 2.f * a * adjin[i * 14 + j];
        W[j][i] = 2.f * (1.f - a) * adjin[j * 14 + i];
    }
    __syncthreads();
    if (c < 14) {
        float s = 0.f;
#pragma unroll
        for (int j = 0; j < 14; j++) s += fabsf(W[c][j]);
        rn[c] = 1.f / fmaxf(s, 1e-12f);
    }
    __syncthreads();

    // aggregate in fp32, pack to fp16
    __half* ag = g_Ag + ((size_t)n * KK) * CC + c;
#pragma unroll
    for (int i = 0; i < 14; i++) {
        float acc = 0.f;
#pragma unroll
        for (int j = 0; j < 14; j++) acc += W[i][j] * xv[j];
        ag[i * CC] = __float2half(acc * rn[i]);
    }
}

// ---------------- fused dual fp16 GEMM: out = relu(Ag@Wm^T) + Ax@Wo^T ----------------
// Block M=64 x N=128 (both matrices), 8 warps (2m x 4n), warp 32x32 per matrix.
#define S_AX 0
#define S_AG 8192
#define S_BO 16384
#define S_BM 32768
#define STG  49152
#define SMEM_G (2 * STG)   // 98304

__device__ __forceinline__ void cpa16(uint32_t dst, const void* src) {
    asm volatile("cp.async.cg.shared.global [%0], [%1], 16;" :: "r"(dst), "l"(src));
}
#define LDSM_X4(r, addr)                                                      \
    asm volatile("ldmatrix.sync.aligned.m8n8.x4.shared.b16 {%0,%1,%2,%3}, [%4];" \
                 : "=r"((r)[0]), "=r"((r)[1]), "=r"((r)[2]), "=r"((r)[3])     \
                 : "r"(addr))
#define MMA_F16(Cr, A0, A1, A2, A3, B0, B1)                                   \
    asm volatile("mma.sync.aligned.m16n8k16.row.col.f32.f16.f16.f32 "          \
                 "{%0,%1,%2,%3}, {%4,%5,%6,%7}, {%8,%9}, {%0,%1,%2,%3};\n"     \
                 : "+f"(Cr[0]), "+f"(Cr[1]), "+f"(Cr[2]), "+f"(Cr[3])          \
                 : "r"(A0), "r"(A1), "r"(A2), "r"(A3), "r"(B0), "r"(B1))

__device__ __forceinline__ void g_load_chunk(uint32_t sb, int stg, int t,
                                             int m0, int o0, int tid) {
    uint32_t base = sb + (uint32_t)stg * STG;
    const __half* Ax = g_Ah + (size_t)m0 * CC + t * 64;
    const __half* Ag = g_Ag + (size_t)m0 * CC + t * 64;
    const __half* Bo = g_Bh + t * 64;
    const __half* Bm = g_Bh + (size_t)OO * CC + t * 64;
#pragma unroll
    for (int i = 0; i < 2; i++) {     // A streams: 512 x 16B each
        int idx = tid + i * 256;
        int r = idx >> 3, c = idx & 7;
        uint32_t off = (uint32_t)r * 128 + (uint32_t)c * 16;
        uint32_t sw = off ^ ((off >> 3) & 0x70);
        cpa16(base + S_AX + sw, Ax + (size_t)r * CC + c * 8);
        cpa16(base + S_AG + sw, Ag + (size_t)r * CC + c * 8);
    }
#pragma unroll
    for (int i = 0; i < 4; i++) {     // B streams: 1024 x 16B each
        int idx = tid + i * 256;
        int r = idx >> 3, c = idx & 7;
        uint32_t off = (uint32_t)r * 128 + (uint32_t)c * 16;
        uint32_t sw = off ^ ((off >> 3) & 0x70);
        cpa16(base + S_BO + sw, Bo + (size_t)(o0 + r) * CC + c * 8);
        cpa16(base + S_BM + sw, Bm + (size_t)(o0 + r) * CC + c * 8);
    }
}

__global__ __launch_bounds__(256, 2) void k_gemm(float* __restrict__ out) {
    extern __shared__ char smem[];
    uint32_t sb = (uint32_t)__cvta_generic_to_shared(smem);
    int tid = threadIdx.x;
    int w = tid >> 5, l = tid & 31;
    int wm = w & 1;        // m half (32 rows)
    int wn = w >> 1;       // n quarter (32 cols)
    int m0 = blockIdx.x * 64;
    int o0 = blockIdx.y * 128;
    int lr = l & 15, lh = l >> 4;

    float accO[2][4][4], accM[2][4][4];
#pragma unroll
    for (int mt = 0; mt < 2; mt++)
#pragma unroll
        for (int nt = 0; nt < 4; nt++)
#pragma unroll
            for (int i = 0; i < 4; i++) { accO[mt][nt][i] = 0.f; accM[mt][nt][i] = 0.f; }

    g_load_chunk(sb, 0, 0, m0, o0, tid);
    asm volatile("cp.async.commit_group;" ::: "memory");
    g_load_chunk(sb, 1, 1, m0, o0, tid);
    asm volatile("cp.async.commit_group;" ::: "memory");

    const int NCH = CC / 64;   // 8
    for (int t = 0; t < NCH; t++) {
        int b = t & 1;
        if (t < NCH - 1) asm volatile("cp.async.wait_group 1;" ::: "memory");
        else             asm volatile("cp.async.wait_group 0;" ::: "memory");
        __syncthreads();

        uint32_t base = sb + (uint32_t)b * STG;
#pragma unroll
        for (int ks = 0; ks < 4; ks++) {
            uint32_t arow = (uint32_t)(wm * 32 + lr) * 128 + (uint32_t)lh * 16 + ks * 32;
            uint32_t brow = (uint32_t)(wn * 32 + lr) * 128 + (uint32_t)lh * 16 + ks * 32;
            uint32_t a0 = arow ^ ((arow >> 3) & 0x70);
            uint32_t a1 = (arow + 16 * 128) ^ (((arow + 16 * 128) >> 3) & 0x70);
            uint32_t b0 = brow ^ ((brow >> 3) & 0x70);
            uint32_t b1 = (brow + 16 * 128) ^ (((brow + 16 * 128) >> 3) & 0x70);
            {   // original stream: Ax @ Wo
                uint32_t af[2][4], bf[2][4];
                LDSM_X4(af[0], base + S_AX + a0);
                LDSM_X4(af[1], base + S_AX + a1);
                LDSM_X4(bf[0], base + S_BO + b0);
                LDSM_X4(bf[1], base + S_BO + b1);
#pragma unroll
                for (int mt = 0; mt < 2; mt++)
#pragma unroll
                    for (int i = 0; i < 2; i++) {
                        MMA_F16(accO[mt][2 * i],     af[mt][0], af[mt][1], af[mt][2], af[mt][3], bf[i][0], bf[i][2]);
                        MMA_F16(accO[mt][2 * i + 1], af[mt][0], af[mt][1], af[mt][2], af[mt][3], bf[i][1], bf[i][3]);
                    }
            }
            {   // merged stream: Ag @ Wm
                uint32_t af[2][4], bf[2][4];
                LDSM_X4(af[0], base + S_AG + a0);
                LDSM_X4(af[1], base + S_AG + a1);
                LDSM_X4(bf[0], base + S_BM + b0);
                LDSM_X4(bf[1], base + S_BM + b1);
#pragma unroll
                for (int mt = 0; mt < 2; mt++)
#pragma unroll
                    for (int i = 0; i < 2; i++) {
                        MMA_F16(accM[mt][2 * i],     af[mt][0], af[mt][1], af[mt][2], af[mt][3], bf[i][0], bf[i][2]);
                        MMA_F16(accM[mt][2 * i + 1], af[mt][0], af[mt][1], af[mt][2], af[mt][3], bf[i][1], bf[i][3]);
                    }
            }
        }
        __syncthreads();

        if (t + 2 < NCH) {
            g_load_chunk(sb, b, t + 2, m0, o0, tid);
            asm volatile("cp.async.commit_group;" ::: "memory");
        }
    }

    // fused epilogue: out = relu(merged) + original
    int gid = l >> 2, tig = l & 3;
#pragma unroll
    for (int mt = 0; mt < 2; mt++) {
#pragma unroll
        for (int nt = 0; nt < 4; nt++) {
            float* p0 = out + (size_t)(m0 + wm * 32 + mt * 16 + gid) * OO + o0 + wn * 32 + nt * 8 + tig * 2;
            float* p1 = p0 + 8 * OO;
            *(float2*)p0 = make_float2(fmaxf(accM[mt][nt][0], 0.f) + accO[mt][nt][0],
                                       fmaxf(accM[mt][nt][1], 0.f) + accO[mt][nt][1]);
            *(float2*)p1 = make_float2(fmaxf(accM[mt][nt][2], 0.f) + accO[mt][nt][2],
                                       fmaxf(accM[mt][nt][3], 0.f) + accO[mt][nt][3]);
        }
    }
}

// ---------------- launch ----------------
extern "C" void kernel_launch(void* const* d_in, const int* in_sizes, int n_in,
                              void* d_out, int out_size) {
    const float* x     = (const float*)d_in[0];
    const float* adj   = (const float*)d_in[1];
    const int*   ei    = (const int*)d_in[2];
    const int*   ej    = (const int*)d_in[3];
    const float* gamma = (const float*)d_in[4];
    const float* beta  = (const float*)d_in[5];
    const float* wdir  = (const float*)d_in[6];
    const float* Wm    = (const float*)d_in[7];
    const float* Wo    = (const float*)d_in[8];
    float* out = (float*)d_out;

    cudaFuncSetAttribute(k_gemm, cudaFuncAttributeMaxDynamicSharedMemorySize, SMEM_G);

    k_zero<<<1, CC>>>();
    k_packw<<<(OO * CC) / 1024, 256>>>(Wm, Wo);
    k_stats<<<NN / 8, CC>>>(x);
    k_adjW<<<NN, CC>>>(x, adj, ei, ej, gamma, beta, wdir);

    dim3 grid(MTOT / 64, OO / 128);   // 448 x 4
    k_gemm<<<grid, 256, SMEM_G>>>(out);
}

// round 8
// speedup vs baseline: 2.4102x; 1.0134x over previous
#include <cuda_runtime.h>
#include <cuda_fp16.h>
#include <cstdint>
#include <stdint.h>
#include <math.h>

#define NN 2048
#define KK 14
#define CC 512
#define OO 512
#define EE 78
#define BN_EPS 1e-5f
#define MTOT (NN * KK)     // 28672

// ---------------- device scratch ----------------
__device__ float g_S1[CC];
__device__ float g_Q[CC];
__device__ __half g_Ah[(size_t)MTOT * CC];     // fp16 X    (28 MB)
__device__ __half g_Ag[(size_t)MTOT * CC];     // fp16 agg  (28 MB)
__device__ __half g_Bh[2ull * OO * CC];        // fp16 Wo(0), Wm(1)

// ---------------- kernel 0: zero accumulators ----------------
__global__ void k_zero() {
    int c = threadIdx.x;
    g_S1[c] = 0.f;
    g_Q[c]  = 0.f;
}

// ---------------- pack weights to fp16 ----------------
__global__ __launch_bounds__(256) void k_packw(const float* __restrict__ Wm,
                                               const float* __restrict__ Wo) {
    int i = blockIdx.x * 1024 + threadIdx.x;
#pragma unroll
    for (int r = 0; r < 4; r++, i += 256) {
        g_Bh[i]            = __float2half(Wo[i]);
        g_Bh[OO * CC + i]  = __float2half(Wm[i]);
    }
}

// ---------------- per-channel BN statistics + fp16 pack of X ----------------
__global__ __launch_bounds__(512) void k_stats(const float* __restrict__ x) {
    int c = threadIdx.x;
    int n0 = blockIdx.x * 8;
    float s1a = 0.f, qa = 0.f;
    for (int r = 0; r < 8; r++) {
        int n = n0 + r;
        const float* p = x + (size_t)n * (KK * CC) + c;
        __half* ah = g_Ah + ((size_t)n * KK) * CC + c;
        float g = p[13 * CC];
        ah[13 * CC] = __float2half(g);
        float s1 = 0.f, s2 = 0.f, ws = 0.f;
#pragma unroll
        for (int k = 0; k < 13; k++) {
            float v = p[k * CC];
            ah[k * CC] = __float2half(v);
            float d = fabsf(v - g);
            s1 += d;
            s2 += d * d;
            ws += (float)(12 - 2 * k) * d;
        }
        s1a += ws;
        qa  += 13.f * s2 - s1 * s1;
    }
    atomicAdd(&g_S1[c], s1a);
    atomicAdd(&g_Q[c],  qa);
}

// ---------------- adjacency + aggregation (smem-transpose reduction) ----------------
__global__ __launch_bounds__(512) void k_adjW(const float* __restrict__ x,
                                              const float* __restrict__ adjin,
                                              const int* __restrict__ ei,
                                              const int* __restrict__ ej,
                                              const float* __restrict__ gamma,
                                              const float* __restrict__ beta,
                                              const float* __restrict__ wdir) {
    int n = blockIdx.x;
    int c = threadIdx.x;
    int lane = c & 31, warp = c >> 5;

    __shared__ float sd[13][CC];     // 26.6 KB transpose buffer
    __shared__ float red[16];
    __shared__ float s_cst;
    __shared__ float sp[13];
    __shared__ float W[14][14];
    __shared__ float rn[14];

    // --- inline finalize: u[c] and cst from global stats ---
    const float inv = 1.f / (float)((size_t)NN * EE);
    float mean = 15.f * g_S1[c] * inv;
    float ms   = 225.f * g_Q[c] * inv;
    float var  = ms - mean * mean;
    float w    = wdir[c];
    float u    = gamma[c] * rsqrtf(var + BN_EPS) * w;
    float part = beta[c] * w - mean * u;
#pragma unroll
    for (int off = 16; off > 0; off >>= 1)
        part += __shfl_xor_sync(0xffffffffu, part, off);
    if (lane == 0) red[warp] = part;

    const float* p = x + (size_t)n * (KK * CC) + c;
    float xv[14];
#pragma unroll
    for (int k = 0; k < 14; k++) xv[k] = p[k * CC];
    float g = xv[13];

    // stage weighted distances into smem (transpose layout)
#pragma unroll
    for (int k = 0; k < 13; k++) sd[k][c] = fabsf(xv[k] - g) * u;
    if (c < 196) W[c / 14][c % 14] = adjin[c];
    __syncthreads();

    if (c == 0) {
        float s = 0.f;
#pragma unroll
        for (int i = 0; i < 16; i++) s += red[i];
        s_cst = s;
    }
    // warp k (k<13) reduces sd[k][0..511]
    if (warp < 13) {
        float s = 0.f;
#pragma unroll
        for (int i = 0; i < 16; i++) s += sd[warp][lane + 32 * i];
        s += __shfl_xor_sync(0xffffffffu, s, 16);
        s += __shfl_xor_sync(0xffffffffu, s, 8);
        s += __shfl_xor_sync(0xffffffffu, s, 4);
        s += __shfl_xor_sync(0xffffffffu, s, 2);
        s += __shfl_xor_sync(0xffffffffu, s, 1);
        if (lane == 0) sp[warp] = s;
    }
    __syncthreads();

    if (c < EE) {
        int i = ei[c], j = ej[c];
        float z = 15.f * (sp[i] - sp[j]) + s_cst;
        float a = 1.f / (1.f + expf(-4.f * z));
        W[i][j] = 2.f * a * adjin[i * 14 + j];
        W[j][i] = 2.f * (1.f - a) * adjin[j * 14 + i];
    }
    __syncthreads();
    if (c < 14) {
        float s = 0.f;
#pragma unroll
        for (int j = 0; j < 14; j++) s += fabsf(W[c][j]);
        rn[c] = 1.f / fmaxf(s, 1e-12f);
    }
    __syncthreads();

    // aggregate in fp32, pack to fp16
    __half* ag = g_Ag + ((size_t)n * KK) * CC + c;
#pragma unroll
    for (int i = 0; i < 14; i++) {
        float acc = 0.f;
#pragma unroll
        for (int j = 0; j < 14; j++) acc += W[i][j] * xv[j];
        ag[i * CC] = __float2half(acc * rn[i]);
    }
}

// ---------------- fused dual fp16 GEMM: out = relu(Ag@Wm^T) + Ax@Wo^T ----------------
#define S_AX 0
#define S_AG 8192
#define S_BO 16384
#define S_BM 32768
#define STG  49152
#define SMEM_G (2 * STG)   // 98304

__device__ __forceinline__ void cpa16(uint32_t dst, const void* src) {
    asm volatile("cp.async.cg.shared.global [%0], [%1], 16;" :: "r"(dst), "l"(src));
}
#define LDSM_X4(r, addr)                                                      \
    asm volatile("ldmatrix.sync.aligned.m8n8.x4.shared.b16 {%0,%1,%2,%3}, [%4];" \
                 : "=r"((r)[0]), "=r"((r)[1]), "=r"((r)[2]), "=r"((r)[3])     \
                 : "r"(addr))
#define MMA_F16(Cr, A0, A1, A2, A3, B0, B1)                                   \
    asm volatile("mma.sync.aligned.m16n8k16.row.col.f32.f16.f16.f32 "          \
                 "{%0,%1,%2,%3}, {%4,%5,%6,%7}, {%8,%9}, {%0,%1,%2,%3};\n"     \
                 : "+f"(Cr[0]), "+f"(Cr[1]), "+f"(Cr[2]), "+f"(Cr[3])          \
                 : "r"(A0), "r"(A1), "r"(A2), "r"(A3), "r"(B0), "r"(B1))

__device__ __forceinline__ void g_load_chunk(uint32_t sb, int stg, int t,
                                             int m0, int o0, int tid) {
    uint32_t base = sb + (uint32_t)stg * STG;
    const __half* Ax = g_Ah + (size_t)m0 * CC + t * 64;
    const __half* Ag = g_Ag + (size_t)m0 * CC + t * 64;
    const __half* Bo = g_Bh + t * 64;
    const __half* Bm = g_Bh + (size_t)OO * CC + t * 64;
#pragma unroll
    for (int i = 0; i < 2; i++) {
        int idx = tid + i * 256;
        int r = idx >> 3, c = idx & 7;
        uint32_t off = (uint32_t)r * 128 + (uint32_t)c * 16;
        uint32_t sw = off ^ ((off >> 3) & 0x70);
        cpa16(base + S_AX + sw, Ax + (size_t)r * CC + c * 8);
        cpa16(base + S_AG + sw, Ag + (size_t)r * CC + c * 8);
    }
#pragma unroll
    for (int i = 0; i < 4; i++) {
        int idx = tid + i * 256;
        int r = idx >> 3, c = idx & 7;
        uint32_t off = (uint32_t)r * 128 + (uint32_t)c * 16;
        uint32_t sw = off ^ ((off >> 3) & 0x70);
        cpa16(base + S_BO + sw, Bo + (size_t)(o0 + r) * CC + c * 8);
        cpa16(base + S_BM + sw, Bm + (size_t)(o0 + r) * CC + c * 8);
    }
}

__global__ __launch_bounds__(256, 2) void k_gemm(float* __restrict__ out) {
    extern __shared__ char smem[];
    uint32_t sb = (uint32_t)__cvta_generic_to_shared(smem);
    int tid = threadIdx.x;
    int w = tid >> 5, l = tid & 31;
    int wm = w & 1;
    int wn = w >> 1;
    int m0 = blockIdx.x * 64;
    int o0 = blockIdx.y * 128;
    int lr = l & 15, lh = l >> 4;

    float accO[2][4][4], accM[2][4][4];
#pragma unroll
    for (int mt = 0; mt < 2; mt++)
#pragma unroll
        for (int nt = 0; nt < 4; nt++)
#pragma unroll
            for (int i = 0; i < 4; i++) { accO[mt][nt][i] = 0.f; accM[mt][nt][i] = 0.f; }

    g_load_chunk(sb, 0, 0, m0, o0, tid);
    asm volatile("cp.async.commit_group;" ::: "memory");
    g_load_chunk(sb, 1, 1, m0, o0, tid);
    asm volatile("cp.async.commit_group;" ::: "memory");

    const int NCH = CC / 64;   // 8
    for (int t = 0; t < NCH; t++) {
        int b = t & 1;
        if (t < NCH - 1) asm volatile("cp.async.wait_group 1;" ::: "memory");
        else             asm volatile("cp.async.wait_group 0;" ::: "memory");
        __syncthreads();

        uint32_t base = sb + (uint32_t)b * STG;
#pragma unroll
        for (int ks = 0; ks < 4; ks++) {
            uint32_t arow = (uint32_t)(wm * 32 + lr) * 128 + (uint32_t)lh * 16 + ks * 32;
            uint32_t brow = (uint32_t)(wn * 32 + lr) * 128 + (uint32_t)lh * 16 + ks * 32;
            uint32_t a0 = arow ^ ((arow >> 3) & 0x70);
            uint32_t a1 = (arow + 16 * 128) ^ (((arow + 16 * 128) >> 3) & 0x70);
            uint32_t b0 = brow ^ ((brow >> 3) & 0x70);
            uint32_t b1 = (brow + 16 * 128) ^ (((brow + 16 * 128) >> 3) & 0x70);
            {
                uint32_t af[2][4], bf[2][4];
                LDSM_X4(af[0], base + S_AX + a0);
                LDSM_X4(af[1], base + S_AX + a1);
                LDSM_X4(bf[0], base + S_BO + b0);
                LDSM_X4(bf[1], base + S_BO + b1);
#pragma unroll
                for (int mt = 0; mt < 2; mt++)
#pragma unroll
                    for (int i = 0; i < 2; i++) {
                        MMA_F16(accO[mt][2 * i],     af[mt][0], af[mt][1], af[mt][2], af[mt][3], bf[i][0], bf[i][2]);
                        MMA_F16(accO[mt][2 * i + 1], af[mt][0], af[mt][1], af[mt][2], af[mt][3], bf[i][1], bf[i][3]);
                    }
            }
            {
                uint32_t af[2][4], bf[2][4];
                LDSM_X4(af[0], base + S_AG + a0);
                LDSM_X4(af[1], base + S_AG + a1);
                LDSM_X4(bf[0], base + S_BM + b0);
                LDSM_X4(bf[1], base + S_BM + b1);
#pragma unroll
                for (int mt = 0; mt < 2; mt++)
#pragma unroll
                    for (int i = 0; i < 2; i++) {
                        MMA_F16(accM[mt][2 * i],     af[mt][0], af[mt][1], af[mt][2], af[mt][3], bf[i][0], bf[i][2]);
                        MMA_F16(accM[mt][2 * i + 1], af[mt][0], af[mt][1], af[mt][2], af[mt][3], bf[i][1], bf[i][3]);
                    }
            }
        }
        __syncthreads();

        if (t + 2 < NCH) {
            g_load_chunk(sb, b, t + 2, m0, o0, tid);
            asm volatile("cp.async.commit_group;" ::: "memory");
        }
    }

    int gid = l >> 2, tig = l & 3;
#pragma unroll
    for (int mt = 0; mt < 2; mt++) {
#pragma unroll
        for (int nt = 0; nt < 4; nt++) {
            float* p0 = out + (size_t)(m0 + wm * 32 + mt * 16 + gid) * OO + o0 + wn * 32 + nt * 8 + tig * 2;
            float* p1 = p0 + 8 * OO;
            *(float2*)p0 = make_float2(fmaxf(accM[mt][nt][0], 0.f) + accO[mt][nt][0],
                                       fmaxf(accM[mt][nt][1], 0.f) + accO[mt][nt][1]);
            *(float2*)p1 = make_float2(fmaxf(accM[mt][nt][2], 0.f) + accO[mt][nt][2],
                                       fmaxf(accM[mt][nt][3], 0.f) + accO[mt][nt][3]);
        }
    }
}

// ---------------- launch ----------------
extern "C" void kernel_launch(void* const* d_in, const int* in_sizes, int n_in,
                              void* d_out, int out_size) {
    const float* x     = (const float*)d_in[0];
    const float* adj   = (const float*)d_in[1];
    const int*   ei    = (const int*)d_in[2];
    const int*   ej    = (const int*)d_in[3];
    const float* gamma = (const float*)d_in[4];
    const float* beta  = (const float*)d_in[5];
    const float* wdir  = (const float*)d_in[6];
    const float* Wm    = (const float*)d_in[7];
    const float* Wo    = (const float*)d_in[8];
    float* out = (float*)d_out;

    cudaFuncSetAttribute(k_gemm, cudaFuncAttributeMaxDynamicSharedMemorySize, SMEM_G);

    k_zero<<<1, CC>>>();
    k_packw<<<(OO * CC) / 1024, 256>>>(Wm, Wo);
    k_stats<<<NN / 8, CC>>>(x);
    k_adjW<<<NN, CC>>>(x, adj, ei, ej, gamma, beta, wdir);

    dim3 grid(MTOT / 64, OO / 128);   // 448 x 4
    k_gemm<<<grid, 256, SMEM_G>>>(out);
}

// round 9
// speedup vs baseline: 2.4811x; 1.0294x over previous
#include <cuda_runtime.h>
#include <cuda_fp16.h>
#include <cstdint>
#include <stdint.h>
#include <math.h>

#define NN 2048
#define KK 14
#define CC 512
#define OO 512
#define EE 78
#define BN_EPS 1e-5f
#define MTOT (NN * KK)     // 28672

// ---------------- device scratch ----------------
__device__ float g_S1[CC];
__device__ float g_Q[CC];
__device__ __half g_Ah[(size_t)MTOT * CC];     // fp16 X    (28 MB)
__device__ __half g_Ag[(size_t)MTOT * CC];     // fp16 agg  (28 MB)
__device__ __half g_Bh[2ull * OO * CC];        // fp16 Wo(0), Wm(1)

// ---------------- pack weights to fp16 (+ zero stats in block 0) ----------------
__global__ __launch_bounds__(256) void k_packw(const float* __restrict__ Wm,
                                               const float* __restrict__ Wo) {
    if (blockIdx.x == 0) {
        int t = threadIdx.x;
        g_S1[t] = 0.f; g_S1[t + 256] = 0.f;
        g_Q[t]  = 0.f; g_Q[t + 256]  = 0.f;
    }
    int i = blockIdx.x * 1024 + threadIdx.x;
#pragma unroll
    for (int r = 0; r < 4; r++, i += 256) {
        g_Bh[i]           = __float2half(Wo[i]);
        g_Bh[OO * CC + i] = __float2half(Wm[i]);
    }
}

// ---------------- per-channel BN statistics + fp16 pack of X ----------------
__global__ __launch_bounds__(512) void k_stats(const float* __restrict__ x) {
    int c = threadIdx.x;
    int n0 = blockIdx.x * 8;
    float s1a = 0.f, qa = 0.f;
    for (int r = 0; r < 8; r++) {
        int n = n0 + r;
        const float* p = x + (size_t)n * (KK * CC) + c;
        __half* ah = g_Ah + ((size_t)n * KK) * CC + c;
        float g = p[13 * CC];
        ah[13 * CC] = __float2half(g);
        float s1 = 0.f, s2 = 0.f, ws = 0.f;
#pragma unroll
        for (int k = 0; k < 13; k++) {
            float v = p[k * CC];
            ah[k * CC] = __float2half(v);
            float d = fabsf(v - g);
            s1 += d;
            s2 += d * d;
            ws += (float)(12 - 2 * k) * d;
        }
        s1a += ws;
        qa  += 13.f * s2 - s1 * s1;
    }
    atomicAdd(&g_S1[c], s1a);
    atomicAdd(&g_Q[c],  qa);
}

// ---------------- adjacency + aggregation ----------------
// occupancy-tuned: 3 CTAs/SM, W rows padded to float4x4 with rn folded in.
__global__ __launch_bounds__(512, 3) void k_adjW(const float* __restrict__ x,
                                                 const float* __restrict__ adjin,
                                                 const int* __restrict__ ei,
                                                 const int* __restrict__ ej,
                                                 const float* __restrict__ gamma,
                                                 const float* __restrict__ beta,
                                                 const float* __restrict__ wdir) {
    int n = blockIdx.x;
    int c = threadIdx.x;
    int lane = c & 31, warp = c >> 5;

    __shared__ float sd[13][CC];     // 26.6 KB transpose buffer
    __shared__ float red[16];
    __shared__ float s_cst;
    __shared__ float sp[13];
    __shared__ float W[14][14];
    __shared__ float rn[14];
    __shared__ float4 W4[14][4];     // rn-folded, zero-padded rows

    // --- inline finalize: u[c] and cst from global stats ---
    const float inv = 1.f / (float)((size_t)NN * EE);
    float mean = 15.f * g_S1[c] * inv;
    float ms   = 225.f * g_Q[c] * inv;
    float var  = ms - mean * mean;
    float w    = wdir[c];
    float u    = gamma[c] * rsqrtf(var + BN_EPS) * w;
    float part = beta[c] * w - mean * u;
#pragma unroll
    for (int off = 16; off > 0; off >>= 1)
        part += __shfl_xor_sync(0xffffffffu, part, off);
    if (lane == 0) red[warp] = part;

    // phase A: weighted distances into smem (x values NOT kept live)
    const float* p = x + (size_t)n * (KK * CC) + c;
    {
        float g = p[13 * CC];
#pragma unroll
        for (int k = 0; k < 13; k++)
            sd[k][c] = fabsf(p[k * CC] - g) * u;
    }
    if (c < 196) W[c / 14][c % 14] = adjin[c];
    __syncthreads();

    if (c == 0) {
        float s = 0.f;
#pragma unroll
        for (int i = 0; i < 16; i++) s += red[i];
        s_cst = s;
    }
    if (warp < 13) {
        float s = 0.f;
#pragma unroll
        for (int i = 0; i < 16; i++) s += sd[warp][lane + 32 * i];
        s += __shfl_xor_sync(0xffffffffu, s, 16);
        s += __shfl_xor_sync(0xffffffffu, s, 8);
        s += __shfl_xor_sync(0xffffffffu, s, 4);
        s += __shfl_xor_sync(0xffffffffu, s, 2);
        s += __shfl_xor_sync(0xffffffffu, s, 1);
        if (lane == 0) sp[warp] = s;
    }
    __syncthreads();

    if (c < EE) {
        int i = ei[c], j = ej[c];
        float z = 15.f * (sp[i] - sp[j]) + s_cst;
        float a = 1.f / (1.f + expf(-4.f * z));
        W[i][j] = 2.f * a * adjin[i * 14 + j];
        W[j][i] = 2.f * (1.f - a) * adjin[j * 14 + i];
    }
    __syncthreads();
    if (c < 14) {
        float s = 0.f;
#pragma unroll
        for (int j = 0; j < 14; j++) s += fabsf(W[c][j]);
        rn[c] = 1.f / fmaxf(s, 1e-12f);
    }
    __syncthreads();
    if (c < 56) {   // build padded rn-folded rows
        int i = c >> 2, q = c & 3;
        int j = q * 4;
        float r = rn[i];
        float4 v;
        v.x = W[i][j] * r;
        v.y = (j + 1 < 14) ? W[i][j + 1] * r : 0.f;
        v.z = (j + 2 < 14) ? W[i][j + 2] * r : 0.f;
        v.w = (j + 3 < 14) ? W[i][j + 3] * r : 0.f;
        W4[i][q] = v;
    }
    __syncthreads();

    // phase B: reload x (L1-hot), aggregate via float4 rows, pack to fp16
    float xq[16];
#pragma unroll
    for (int k = 0; k < 14; k++) xq[k] = p[k * CC];
    xq[14] = 0.f; xq[15] = 0.f;

    __half* ag = g_Ag + ((size_t)n * KK) * CC + c;
#pragma unroll
    for (int i = 0; i < 14; i++) {
        float acc = 0.f;
#pragma unroll
        for (int q = 0; q < 4; q++) {
            float4 wv = W4[i][q];
            acc += wv.x * xq[4 * q] + wv.y * xq[4 * q + 1]
                 + wv.z * xq[4 * q + 2] + wv.w * xq[4 * q + 3];
        }
        ag[i * CC] = __float2half(acc);
    }
}

// ---------------- fused dual fp16 GEMM: out = relu(Ag@Wm^T) + Ax@Wo^T ----------------
#define S_AX 0
#define S_AG 8192
#define S_BO 16384
#define S_BM 32768
#define STG  49152
#define SMEM_G (2 * STG)   // 98304

__device__ __forceinline__ void cpa16(uint32_t dst, const void* src) {
    asm volatile("cp.async.cg.shared.global [%0], [%1], 16;" :: "r"(dst), "l"(src));
}
#define LDSM_X4(r, addr)                                                      \
    asm volatile("ldmatrix.sync.aligned.m8n8.x4.shared.b16 {%0,%1,%2,%3}, [%4];" \
                 : "=r"((r)[0]), "=r"((r)[1]), "=r"((r)[2]), "=r"((r)[3])     \
                 : "r"(addr))
#define MMA_F16(Cr, A0, A1, A2, A3, B0, B1)                                   \
    asm volatile("mma.sync.aligned.m16n8k16.row.col.f32.f16.f16.f32 "          \
                 "{%0,%1,%2,%3}, {%4,%5,%6,%7}, {%8,%9}, {%0,%1,%2,%3};\n"     \
                 : "+f"(Cr[0]), "+f"(Cr[1]), "+f"(Cr[2]), "+f"(Cr[3])          \
                 : "r"(A0), "r"(A1), "r"(A2), "r"(A3), "r"(B0), "r"(B1))

__device__ __forceinline__ void g_load_chunk(uint32_t sb, int stg, int t,
                                             int m0, int o0, int tid) {
    uint32_t base = sb + (uint32_t)stg * STG;
    const __half* Ax = g_Ah + (size_t)m0 * CC + t * 64;
    const __half* Ag = g_Ag + (size_t)m0 * CC + t * 64;
    const __half* Bo = g_Bh + t * 64;
    const __half* Bm = g_Bh + (size_t)OO * CC + t * 64;
#pragma unroll
    for (int i = 0; i < 2; i++) {
        int idx = tid + i * 256;
        int r = idx >> 3, c = idx & 7;
        uint32_t off = (uint32_t)r * 128 + (uint32_t)c * 16;
        uint32_t sw = off ^ ((off >> 3) & 0x70);
        cpa16(base + S_AX + sw, Ax + (size_t)r * CC + c * 8);
        cpa16(base + S_AG + sw, Ag + (size_t)r * CC + c * 8);
    }
#pragma unroll
    for (int i = 0; i < 4; i++) {
        int idx = tid + i * 256;
        int r = idx >> 3, c = idx & 7;
        uint32_t off = (uint32_t)r * 128 + (uint32_t)c * 16;
        uint32_t sw = off ^ ((off >> 3) & 0x70);
        cpa16(base + S_BO + sw, Bo + (size_t)(o0 + r) * CC + c * 8);
        cpa16(base + S_BM + sw, Bm + (size_t)(o0 + r) * CC + c * 8);
    }
}

__global__ __launch_bounds__(256, 2) void k_gemm(float* __restrict__ out) {
    extern __shared__ char smem[];
    uint32_t sb = (uint32_t)__cvta_generic_to_shared(smem);
    int tid = threadIdx.x;
    int w = tid >> 5, l = tid & 31;
    int wm = w & 1;
    int wn = w >> 1;
    int m0 = blockIdx.x * 64;
    int o0 = blockIdx.y * 128;
    int lr = l & 15, lh = l >> 4;

    float accO[2][4][4], accM[2][4][4];
#pragma unroll
    for (int mt = 0; mt < 2; mt++)
#pragma unroll
        for (int nt = 0; nt < 4; nt++)
#pragma unroll
            for (int i = 0; i < 4; i++) { accO[mt][nt][i] = 0.f; accM[mt][nt][i] = 0.f; }

    g_load_chunk(sb, 0, 0, m0, o0, tid);
    asm volatile("cp.async.commit_group;" ::: "memory");
    g_load_chunk(sb, 1, 1, m0, o0, tid);
    asm volatile("cp.async.commit_group;" ::: "memory");

    const int NCH = CC / 64;   // 8
    for (int t = 0; t < NCH; t++) {
        int b = t & 1;
        if (t < NCH - 1) asm volatile("cp.async.wait_group 1;" ::: "memory");
        else             asm volatile("cp.async.wait_group 0;" ::: "memory");
        __syncthreads();

        uint32_t base = sb + (uint32_t)b * STG;
#pragma unroll
        for (int ks = 0; ks < 4; ks++) {
            uint32_t arow = (uint32_t)(wm * 32 + lr) * 128 + (uint32_t)lh * 16 + ks * 32;
            uint32_t brow = (uint32_t)(wn * 32 + lr) * 128 + (uint32_t)lh * 16 + ks * 32;
            uint32_t a0 = arow ^ ((arow >> 3) & 0x70);
            uint32_t a1 = (arow + 16 * 128) ^ (((arow + 16 * 128) >> 3) & 0x70);
            uint32_t b0 = brow ^ ((brow >> 3) & 0x70);
            uint32_t b1 = (brow + 16 * 128) ^ (((brow + 16 * 128) >> 3) & 0x70);
            {
                uint32_t af[2][4], bf[2][4];
                LDSM_X4(af[0], base + S_AX + a0);
                LDSM_X4(af[1], base + S_AX + a1);
                LDSM_X4(bf[0], base + S_BO + b0);
                LDSM_X4(bf[1], base + S_BO + b1);
#pragma unroll
                for (int mt = 0; mt < 2; mt++)
#pragma unroll
                    for (int i = 0; i < 2; i++) {
                        MMA_F16(accO[mt][2 * i],     af[mt][0], af[mt][1], af[mt][2], af[mt][3], bf[i][0], bf[i][2]);
                        MMA_F16(accO[mt][2 * i + 1], af[mt][0], af[mt][1], af[mt][2], af[mt][3], bf[i][1], bf[i][3]);
                    }
            }
            {
                uint32_t af[2][4], bf[2][4];
                LDSM_X4(af[0], base + S_AG + a0);
                LDSM_X4(af[1], base + S_AG + a1);
                LDSM_X4(bf[0], base + S_BM + b0);
                LDSM_X4(bf[1], base + S_BM + b1);
#pragma unroll
                for (int mt = 0; mt < 2; mt++)
#pragma unroll
                    for (int i = 0; i < 2; i++) {
                        MMA_F16(accM[mt][2 * i],     af[mt][0], af[mt][1], af[mt][2], af[mt][3], bf[i][0], bf[i][2]);
                        MMA_F16(accM[mt][2 * i + 1], af[mt][0], af[mt][1], af[mt][2], af[mt][3], bf[i][1], bf[i][3]);
                    }
            }
        }
        __syncthreads();

        if (t + 2 < NCH) {
            g_load_chunk(sb, b, t + 2, m0, o0, tid);
            asm volatile("cp.async.commit_group;" ::: "memory");
        }
    }

    int gid = l >> 2, tig = l & 3;
#pragma unroll
    for (int mt = 0; mt < 2; mt++) {
#pragma unroll
        for (int nt = 0; nt < 4; nt++) {
            float* p0 = out + (size_t)(m0 + wm * 32 + mt * 16 + gid) * OO + o0 + wn * 32 + nt * 8 + tig * 2;
            float* p1 = p0 + 8 * OO;
            *(float2*)p0 = make_float2(fmaxf(accM[mt][nt][0], 0.f) + accO[mt][nt][0],
                                       fmaxf(accM[mt][nt][1], 0.f) + accO[mt][nt][1]);
            *(float2*)p1 = make_float2(fmaxf(accM[mt][nt][2], 0.f) + accO[mt][nt][2],
                                       fmaxf(accM[mt][nt][3], 0.f) + accO[mt][nt][3]);
        }
    }
}

// ---------------- launch ----------------
extern "C" void kernel_launch(void* const* d_in, const int* in_sizes, int n_in,
                              void* d_out, int out_size) {
    const float* x     = (const float*)d_in[0];
    const float* adj   = (const float*)d_in[1];
    const int*   ei    = (const int*)d_in[2];
    const int*   ej    = (const int*)d_in[3];
    const float* gamma = (const float*)d_in[4];
    const float* beta  = (const float*)d_in[5];
    const float* wdir  = (const float*)d_in[6];
    const float* Wm    = (const float*)d_in[7];
    const float* Wo    = (const float*)d_in[8];
    float* out = (float*)d_out;

    cudaFuncSetAttribute(k_gemm, cudaFuncAttributeMaxDynamicSharedMemorySize, SMEM_G);

    k_packw<<<(OO * CC) / 1024, 256>>>(Wm, Wo);
    k_stats<<<NN / 8, CC>>>(x);
    k_adjW<<<NN, CC>>>(x, adj, ei, ej, gamma, beta, wdir);

    dim3 grid(MTOT / 64, OO / 128);   // 448 x 4
    k_gemm<<<grid, 256, SMEM_G>>>(out);
}